// round 6
// baseline (speedup 1.0000x reference)
#include <cuda_runtime.h>
#include <cuda_fp16.h>
#include <cstdint>

// ---------------- problem dims ----------------
constexpr int B_ = 4, E_ = 8, C_ = 2048, D_ = 1024, F_ = 2816;

// ---------------- device scratch (allocation-free) ----------------
__device__ __half g_xh [(size_t)B_ * E_ * C_ * D_];   // X fp16 [be][C][D]
__device__ __half g_w1t[(size_t)E_ * F_ * D_];        // w1^T fp16 [e][F][D]
__device__ __half g_w3t[(size_t)E_ * F_ * D_];        // w3^T fp16 [e][F][D]
__device__ __half g_w2t[(size_t)E_ * D_ * F_];        // w2^T fp16 [e][D][F]
__device__ __half g_hh [(size_t)B_ * E_ * C_ * F_];   // H fp16 [be][C][F]

// ---------------- PTX helpers ----------------
__device__ __forceinline__ uint32_t smem_u32(const void* p) {
    return (uint32_t)__cvta_generic_to_shared(p);
}
__device__ __forceinline__ void bulk_cp128(uint32_t dst, const void* src, uint32_t mbar) {
    asm volatile(
        "cp.async.bulk.shared::cluster.global.mbarrier::complete_tx::bytes "
        "[%0], [%1], 128, [%2];"
        ::"r"(dst), "l"(src), "r"(mbar) : "memory");
}
__device__ __forceinline__ void mbar_init(uint32_t a, uint32_t cnt) {
    asm volatile("mbarrier.init.shared.b64 [%0], %1;" ::"r"(a), "r"(cnt) : "memory");
}
__device__ __forceinline__ void mbar_expect_tx(uint32_t a, uint32_t bytes) {
    asm volatile("mbarrier.arrive.expect_tx.shared.b64 _, [%0], %1;"
                 ::"r"(a), "r"(bytes) : "memory");
}
__device__ __forceinline__ void mbar_wait(uint32_t a, uint32_t parity) {
    asm volatile(
        "{\n\t.reg .pred P;\n"
        "WL_%=:\n\t"
        "mbarrier.try_wait.parity.acquire.cta.shared::cta.b64 P, [%0], %1, 0x989680;\n\t"
        "@P bra WD_%=;\n\t"
        "bra WL_%=;\n"
        "WD_%=:\n\t}"
        ::"r"(a), "r"(parity) : "memory");
}
__device__ __forceinline__ void ldsm4(uint32_t* r, uint32_t addr) {
    asm volatile("ldmatrix.sync.aligned.m8n8.x4.shared.b16 {%0,%1,%2,%3}, [%4];"
                 : "=r"(r[0]), "=r"(r[1]), "=r"(r[2]), "=r"(r[3])
                 : "r"(addr));
}
__device__ __forceinline__ void mma16816(float* d, const uint32_t* a, uint32_t b0, uint32_t b1) {
    asm volatile(
        "mma.sync.aligned.m16n8k16.row.col.f32.f16.f16.f32 "
        "{%0,%1,%2,%3}, {%4,%5,%6,%7}, {%8,%9}, {%0,%1,%2,%3};"
        : "+f"(d[0]), "+f"(d[1]), "+f"(d[2]), "+f"(d[3])
        : "r"(a[0]), "r"(a[1]), "r"(a[2]), "r"(a[3]), "r"(b0), "r"(b1));
}

// ---------------- convert kernels ----------------
__global__ void cvt_kernel(const float4* __restrict__ in, __half2* __restrict__ out, int n4) {
    int i = blockIdx.x * 256 + threadIdx.x;
    if (i >= n4) return;
    float4 v = in[i];
    out[2 * i + 0] = __floats2half2_rn(v.x, v.y);
    out[2 * i + 1] = __floats2half2_rn(v.z, v.w);
}

// in: [R, Ccols] fp32 per expert  ->  out: [Ccols, R] fp16 per expert
__global__ void cvtT_kernel(const float* __restrict__ in, __half* __restrict__ out,
                            int R, int Ccols) {
    __shared__ float t[32][33];
    const float* ine  = in  + (size_t)blockIdx.z * R * Ccols;
    __half*      oute = out + (size_t)blockIdx.z * R * Ccols;
    int c0 = blockIdx.x * 32, r0 = blockIdx.y * 32;
    int tx = threadIdx.x, ty = threadIdx.y;   // 32 x 8
#pragma unroll
    for (int i = 0; i < 4; i++)
        t[ty + 8 * i][tx] = ine[(size_t)(r0 + ty + 8 * i) * Ccols + c0 + tx];
    __syncthreads();
#pragma unroll
    for (int i = 0; i < 4; i++)
        oute[(size_t)(c0 + ty + 8 * i) * R + r0 + tx] = __float2half_rn(t[tx][ty + 8 * i]);
}

// ============================================================
// mma.sync GEMM with bulk-async loads.
// 512 threads, CTA tile 128(M) x 256(B-rows), BK=64, 3 stages.
// Loads: 384 x cp.async.bulk of 128B per stage -> mbarrier expect_tx(49152).
// SMEM rows: 64 halfs (128B) at 144B stride -> ldmatrix conflict-free.
// Warp grid 4(M) x 4(N): warp owns 32 M-rows / 64 B-rows.
// GEMM1: B = [128 w1t rows ; 128 w3t rows]; SwiGLU in regs -> H fp16 128x128.
// GEMM2: B = 256 w2t rows -> out fp32 128x256.
// ============================================================
constexpr int ROWB   = 144;
constexpr int STG    = 384 * ROWB;     // 55296 B
constexpr int DYNSM  = 3 * STG;        // 165888 B
constexpr uint32_t STG_TX = 384 * 128; // 49152 bytes per stage

template <int G1>
__global__ __launch_bounds__(512, 1) void gemm_mma(float* __restrict__ out) {
    extern __shared__ __align__(128) char smem[];
    __shared__ __align__(8) uint64_t mbars[3];

    const int tid  = threadIdx.x;
    const int wid  = tid >> 5;
    const int lane = tid & 31;
    const int be   = blockIdx.z, e = be & 7;
    const int m0   = blockIdx.y * 128;
    const int n0   = blockIdx.x * (G1 ? 128 : 256);

    constexpr int LD = G1 ? D_ : F_;
    constexpr int NK = G1 ? (D_ / 64) : (F_ / 64);    // 16 : 44

    const __half* A = (G1 ? g_xh : g_hh) + ((size_t)be * C_ + m0) * LD;
    const __half* B0;
    const __half* B1w = nullptr;
    if (G1) {
        B0  = g_w1t + (size_t)e * F_ * D_ + (size_t)n0 * D_;
        B1w = g_w3t + (size_t)e * F_ * D_ + (size_t)n0 * D_;
    } else {
        B0 = g_w2t + (size_t)e * D_ * F_ + (size_t)n0 * F_;
    }

    const uint32_t sb = smem_u32(smem);
    const uint32_t mb = smem_u32(mbars);

    if (tid == 0) {
#pragma unroll
        for (int i = 0; i < 3; i++) mbar_init(mb + 8 * i, 1);
    }
    __syncthreads();

    // ------- stage issue: 384 rows, one 128B bulk copy per row -------
    auto issue_stage = [&](int s, int k0) {
        if (tid == 0) mbar_expect_tx(mb + 8 * s, STG_TX);
        if (tid < 384) {
            const int r = tid;
            const __half* src;
            if (r < 128) {
                src = A + (size_t)r * LD + k0;
            } else {
                int n = r - 128;
                if (G1)
                    src = (n < 128) ? B0 + (size_t)n * D_ + k0
                                    : B1w + (size_t)(n - 128) * D_ + k0;
                else
                    src = B0 + (size_t)n * F_ + k0;
            }
            bulk_cp128(sb + s * STG + r * ROWB, src, mb + 8 * s);
        }
    };

    issue_stage(0, 0);
    issue_stage(1, 64);

    const int wm = wid >> 2;
    const int wn = wid & 3;
    const int lr = lane & 15;
    const int lk = (lane >> 4) * 16;

    float acc0[2][2][2][4], acc1[2][2][2][4];
#pragma unroll
    for (int a = 0; a < 2; a++)
#pragma unroll
        for (int b = 0; b < 2; b++)
#pragma unroll
            for (int c = 0; c < 2; c++)
#pragma unroll
                for (int q = 0; q < 4; q++) { acc0[a][b][c][q] = 0.f; acc1[a][b][c][q] = 0.f; }

    for (int kt = 0; kt < NK; kt++) {
        const int s = kt % 3;

        __syncthreads();   // all warps done consuming stage kt-1 (buffer (kt+2)%3)
        if (kt + 2 < NK) issue_stage((kt + 2) % 3, (kt + 2) * 64);
        mbar_wait(mb + 8 * s, (kt / 3) & 1);

        const uint32_t sA = sb + s * STG;
        const uint32_t sB = sA + 128 * ROWB;

#pragma unroll
        for (int kk = 0; kk < 4; kk++) {
            uint32_t af[2][4];
#pragma unroll
            for (int mt = 0; mt < 2; mt++)
                ldsm4(af[mt], sA + (wm * 32 + mt * 16 + lr) * ROWB + kk * 32 + lk);

            uint32_t b0r[2][4], b1r[2][4];
#pragma unroll
            for (int nt = 0; nt < 2; nt++) {
                if (G1) {
                    ldsm4(b0r[nt], sB + (wn * 32 + nt * 16 + lr) * ROWB + kk * 32 + lk);
                    ldsm4(b1r[nt], sB + (128 + wn * 32 + nt * 16 + lr) * ROWB + kk * 32 + lk);
                } else {
                    ldsm4(b0r[nt], sB + (wn * 64 + nt * 16 + lr) * ROWB + kk * 32 + lk);
                    ldsm4(b1r[nt], sB + (wn * 64 + 32 + nt * 16 + lr) * ROWB + kk * 32 + lk);
                }
            }
#pragma unroll
            for (int mt = 0; mt < 2; mt++)
#pragma unroll
                for (int nt = 0; nt < 2; nt++)
#pragma unroll
                    for (int hi = 0; hi < 2; hi++) {
                        mma16816(acc0[mt][nt][hi], af[mt], b0r[nt][hi], b0r[nt][hi + 2]);
                        mma16816(acc1[mt][nt][hi], af[mt], b1r[nt][hi], b1r[nt][hi + 2]);
                    }
        }
    }

    // ---------------- epilogue ----------------
    const int rbase = m0 + wm * 32 + (lane >> 2);
    const int c0    = (lane & 3) * 2;

    if (G1) {
#pragma unroll
        for (int mt = 0; mt < 2; mt++) {
#pragma unroll
            for (int h = 0; h < 2; h++) {
                const size_t row = (size_t)be * C_ + rbase + mt * 16 + h * 8;
                __half* orow = g_hh + row * F_ + n0 + wn * 32 + c0;
#pragma unroll
                for (int nt = 0; nt < 2; nt++)
#pragma unroll
                    for (int hi = 0; hi < 2; hi++) {
                        float g0 = acc0[mt][nt][hi][2 * h + 0], g1 = acc0[mt][nt][hi][2 * h + 1];
                        float u0 = acc1[mt][nt][hi][2 * h + 0], u1 = acc1[mt][nt][hi][2 * h + 1];
                        float h0 = u0 * g0 / (1.0f + __expf(-g0));
                        float h1 = u1 * g1 / (1.0f + __expf(-g1));
                        *reinterpret_cast<__half2*>(orow + nt * 16 + hi * 8) =
                            __floats2half2_rn(h0, h1);
                    }
            }
        }
    } else {
#pragma unroll
        for (int mt = 0; mt < 2; mt++) {
#pragma unroll
            for (int h = 0; h < 2; h++) {
                const size_t row = (size_t)be * C_ + rbase + mt * 16 + h * 8;
                float* orow = out + row * D_ + n0 + wn * 64 + c0;
#pragma unroll
                for (int nt = 0; nt < 2; nt++)
#pragma unroll
                    for (int hi = 0; hi < 2; hi++) {
                        *reinterpret_cast<float2*>(orow + nt * 16 + hi * 8) =
                            make_float2(acc0[mt][nt][hi][2 * h + 0], acc0[mt][nt][hi][2 * h + 1]);
                        *reinterpret_cast<float2*>(orow + 32 + nt * 16 + hi * 8) =
                            make_float2(acc1[mt][nt][hi][2 * h + 0], acc1[mt][nt][hi][2 * h + 1]);
                    }
            }
        }
    }
}

// ---------------- launch ----------------
extern "C" void kernel_launch(void* const* d_in, const int* in_sizes, int n_in,
                              void* d_out, int out_size) {
    const float* x  = (const float*)d_in[0];
    const float* w1 = (const float*)d_in[1];
    const float* w3 = (const float*)d_in[2];
    const float* w2 = (const float*)d_in[3];
    float* out = (float*)d_out;

    void *pxh, *pw1t, *pw3t, *pw2t;
    cudaGetSymbolAddress(&pxh,  g_xh);
    cudaGetSymbolAddress(&pw1t, g_w1t);
    cudaGetSymbolAddress(&pw3t, g_w3t);
    cudaGetSymbolAddress(&pw2t, g_w2t);

    cudaFuncSetAttribute(gemm_mma<1>, cudaFuncAttributeMaxDynamicSharedMemorySize, DYNSM);
    cudaFuncSetAttribute(gemm_mma<0>, cudaFuncAttributeMaxDynamicSharedMemorySize, DYNSM);

    const int nx4 = (int)((size_t)B_ * E_ * C_ * D_ / 4);
    cvt_kernel<<<(nx4 + 255) / 256, 256>>>((const float4*)x, (__half2*)pxh, nx4);

    dim3 tb(32, 8);
    cvtT_kernel<<<dim3(F_ / 32, D_ / 32, E_), tb>>>(w1, (__half*)pw1t, D_, F_);
    cvtT_kernel<<<dim3(F_ / 32, D_ / 32, E_), tb>>>(w3, (__half*)pw3t, D_, F_);
    cvtT_kernel<<<dim3(D_ / 32, F_ / 32, E_), tb>>>(w2, (__half*)pw2t, F_, D_);

    gemm_mma<1><<<dim3(F_ / 128, C_ / 128, B_ * E_), 512, DYNSM>>>(nullptr);
    gemm_mma<0><<<dim3(D_ / 256, C_ / 128, B_ * E_), 512, DYNSM>>>(out);
}

// round 7
// speedup vs baseline: 1.2536x; 1.2536x over previous
#include <cuda_runtime.h>
#include <cuda_fp16.h>
#include <cstdint>

// ---------------- problem dims ----------------
constexpr int B_ = 4, E_ = 8, C_ = 2048, D_ = 1024, F_ = 2816;

// ---------------- device scratch (allocation-free) ----------------
__device__ __half g_xh [(size_t)B_ * E_ * C_ * D_];   // X fp16 [be][C][D]
__device__ __half g_w1t[(size_t)E_ * F_ * D_];        // w1^T fp16 [e][F][D]
__device__ __half g_w3t[(size_t)E_ * F_ * D_];        // w3^T fp16 [e][F][D]
__device__ __half g_w2t[(size_t)E_ * D_ * F_];        // w2^T fp16 [e][D][F]
__device__ __half g_hh [(size_t)B_ * E_ * C_ * F_];   // H fp16 [be][C][F]

// ---------------- PTX helpers ----------------
__device__ __forceinline__ uint32_t smem_u32(const void* p) {
    return (uint32_t)__cvta_generic_to_shared(p);
}
__device__ __forceinline__ void cp16(uint32_t saddr, const void* g) {
    asm volatile("cp.async.cg.shared.global [%0], [%1], 16;\n" ::"r"(saddr), "l"(g));
}
__device__ __forceinline__ void cp_commit() {
    asm volatile("cp.async.commit_group;\n");
}
__device__ __forceinline__ void cp_wait2() {
    asm volatile("cp.async.wait_group 2;\n");
}
__device__ __forceinline__ void ldsm4(uint32_t* r, uint32_t addr) {
    asm volatile("ldmatrix.sync.aligned.m8n8.x4.shared.b16 {%0,%1,%2,%3}, [%4];"
                 : "=r"(r[0]), "=r"(r[1]), "=r"(r[2]), "=r"(r[3])
                 : "r"(addr));
}
__device__ __forceinline__ void mma16816(float* d, const uint32_t* a, uint32_t b0, uint32_t b1) {
    asm volatile(
        "mma.sync.aligned.m16n8k16.row.col.f32.f16.f16.f32 "
        "{%0,%1,%2,%3}, {%4,%5,%6,%7}, {%8,%9}, {%0,%1,%2,%3};"
        : "+f"(d[0]), "+f"(d[1]), "+f"(d[2]), "+f"(d[3])
        : "r"(a[0]), "r"(a[1]), "r"(a[2]), "r"(a[3]), "r"(b0), "r"(b1));
}

// ---------------- convert kernels ----------------
__global__ void cvt_kernel(const float4* __restrict__ in, __half2* __restrict__ out, int n4) {
    int i = blockIdx.x * 256 + threadIdx.x;
    if (i >= n4) return;
    float4 v = in[i];
    out[2 * i + 0] = __floats2half2_rn(v.x, v.y);
    out[2 * i + 1] = __floats2half2_rn(v.z, v.w);
}

// in: [R, Ccols] fp32 per expert  ->  out: [Ccols, R] fp16 per expert
__global__ void cvtT_kernel(const float* __restrict__ in, __half* __restrict__ out,
                            int R, int Ccols) {
    __shared__ float t[32][33];
    const float* ine  = in  + (size_t)blockIdx.z * R * Ccols;
    __half*      oute = out + (size_t)blockIdx.z * R * Ccols;
    int c0 = blockIdx.x * 32, r0 = blockIdx.y * 32;
    int tx = threadIdx.x, ty = threadIdx.y;   // 32 x 8
#pragma unroll
    for (int i = 0; i < 4; i++)
        t[ty + 8 * i][tx] = ine[(size_t)(r0 + ty + 8 * i) * Ccols + c0 + tx];
    __syncthreads();
#pragma unroll
    for (int i = 0; i < 4; i++)
        oute[(size_t)(c0 + ty + 8 * i) * R + r0 + tx] = __float2half_rn(t[tx][ty + 8 * i]);
}

// ============================================================
// mma.sync GEMM, 512 threads, CTA tile 128(M) x 256(B-rows), BK=64, 4 stages,
// ONE __syncthreads per k-iter.
// SMEM rows: 64 halfs (128B) at 144B stride -> ldmatrix conflict-free.
// Warp grid 4(M) x 4(N): warp owns 32 M-rows and 64 B-rows.
// GEMM1 (G1=1): B = [128 w1t rows ; 128 w3t rows]; SwiGLU in regs -> H fp16 128x128.
// GEMM2 (G1=0): B = 256 w2t rows -> out fp32 128x256.
// ============================================================
constexpr int ROWB  = 144;
constexpr int STG   = 384 * ROWB;    // 55296 B
constexpr int DYNSM = 4 * STG;       // 221184 B

template <int G1>
__global__ __launch_bounds__(512, 1) void gemm_mma(float* __restrict__ out) {
    extern __shared__ __align__(128) char smem[];

    const int tid  = threadIdx.x;
    const int wid  = tid >> 5;
    const int lane = tid & 31;
    const int be   = blockIdx.z, e = be & 7;
    const int m0   = blockIdx.y * 128;
    const int n0   = blockIdx.x * (G1 ? 128 : 256);

    constexpr int LD = G1 ? D_ : F_;
    constexpr int NK = G1 ? (D_ / 64) : (F_ / 64);    // 16 : 44

    const __half* A = (G1 ? g_xh : g_hh) + ((size_t)be * C_ + m0) * LD;
    const __half* B0;
    const __half* B1w = nullptr;
    if (G1) {
        B0  = g_w1t + (size_t)e * F_ * D_ + (size_t)n0 * D_;
        B1w = g_w3t + (size_t)e * F_ * D_ + (size_t)n0 * D_;
    } else {
        B0 = g_w2t + (size_t)e * D_ * F_ + (size_t)n0 * F_;
    }

    const uint32_t sb = smem_u32(smem);

    // ------- stage loader: 512 threads x 6 cp16 (384 rows x 8 chunks) -------
    auto load_stage = [&](int s, int k0) {
        const uint32_t base = sb + s * STG;
#pragma unroll
        for (int i = 0; i < 6; i++) {
            int t = tid + i * 512;
            int r = t >> 3, c = t & 7;      // r 0..383, c 0..7
            const __half* src;
            if (r < 128) {
                src = A + (size_t)r * LD + k0 + c * 8;
            } else {
                int n = r - 128;            // 0..255
                if (G1)
                    src = (n < 128) ? B0 + (size_t)n * D_ + k0 + c * 8
                                    : B1w + (size_t)(n - 128) * D_ + k0 + c * 8;
                else
                    src = B0 + (size_t)n * F_ + k0 + c * 8;
            }
            cp16(base + r * ROWB + c * 16, src);
        }
    };

    load_stage(0, 0);   cp_commit();
    load_stage(1, 64);  cp_commit();
    load_stage(2, 128); cp_commit();

    const int wm = wid >> 2;           // 0..3 : M rows [wm*32, +32)
    const int wn = wid & 3;            // 0..3
    const int lr = lane & 15;
    const int lk = (lane >> 4) * 16;

    float acc0[2][2][2][4], acc1[2][2][2][4];
#pragma unroll
    for (int a = 0; a < 2; a++)
#pragma unroll
        for (int b = 0; b < 2; b++)
#pragma unroll
            for (int c = 0; c < 2; c++)
#pragma unroll
                for (int q = 0; q < 4; q++) { acc0[a][b][c][q] = 0.f; acc1[a][b][c][q] = 0.f; }

    for (int kt = 0; kt < NK; kt++) {
        const int s = kt & 3;

        cp_wait2();          // stage kt's group complete (this thread)
        __syncthreads();     // stage kt visible to all; all warps finished compute kt-1

        // buffer (kt+3)&3 was last consumed at iter kt-1 -> safe to overwrite now
        if (kt + 3 < NK) load_stage((kt + 3) & 3, (kt + 3) * 64);
        cp_commit();

        const uint32_t sA = sb + s * STG;
        const uint32_t sB = sA + 128 * ROWB;

#pragma unroll
        for (int kk = 0; kk < 4; kk++) {
            uint32_t af[2][4];
#pragma unroll
            for (int mt = 0; mt < 2; mt++)
                ldsm4(af[mt], sA + (wm * 32 + mt * 16 + lr) * ROWB + kk * 32 + lk);

            uint32_t b0r[2][4], b1r[2][4];
#pragma unroll
            for (int nt = 0; nt < 2; nt++) {
                if (G1) {
                    ldsm4(b0r[nt], sB + (wn * 32 + nt * 16 + lr) * ROWB + kk * 32 + lk);
                    ldsm4(b1r[nt], sB + (128 + wn * 32 + nt * 16 + lr) * ROWB + kk * 32 + lk);
                } else {
                    ldsm4(b0r[nt], sB + (wn * 64 + nt * 16 + lr) * ROWB + kk * 32 + lk);
                    ldsm4(b1r[nt], sB + (wn * 64 + 32 + nt * 16 + lr) * ROWB + kk * 32 + lk);
                }
            }
#pragma unroll
            for (int mt = 0; mt < 2; mt++)
#pragma unroll
                for (int nt = 0; nt < 2; nt++)
#pragma unroll
                    for (int hi = 0; hi < 2; hi++) {
                        mma16816(acc0[mt][nt][hi], af[mt], b0r[nt][hi], b0r[nt][hi + 2]);
                        mma16816(acc1[mt][nt][hi], af[mt], b1r[nt][hi], b1r[nt][hi + 2]);
                    }
        }
        // no bottom barrier: next iter's top sync provides the rendezvous
    }

    // ---------------- epilogue ----------------
    const int rbase = m0 + wm * 32 + (lane >> 2);
    const int c0    = (lane & 3) * 2;

    if (G1) {
#pragma unroll
        for (int mt = 0; mt < 2; mt++) {
#pragma unroll
            for (int h = 0; h < 2; h++) {
                const size_t row = (size_t)be * C_ + rbase + mt * 16 + h * 8;
                __half* orow = g_hh + row * F_ + n0 + wn * 32 + c0;
#pragma unroll
                for (int nt = 0; nt < 2; nt++)
#pragma unroll
                    for (int hi = 0; hi < 2; hi++) {
                        float g0 = acc0[mt][nt][hi][2 * h + 0], g1 = acc0[mt][nt][hi][2 * h + 1];
                        float u0 = acc1[mt][nt][hi][2 * h + 0], u1 = acc1[mt][nt][hi][2 * h + 1];
                        float h0 = u0 * g0 / (1.0f + __expf(-g0));
                        float h1 = u1 * g1 / (1.0f + __expf(-g1));
                        *reinterpret_cast<__half2*>(orow + nt * 16 + hi * 8) =
                            __floats2half2_rn(h0, h1);
                    }
            }
        }
    } else {
#pragma unroll
        for (int mt = 0; mt < 2; mt++) {
#pragma unroll
            for (int h = 0; h < 2; h++) {
                const size_t row = (size_t)be * C_ + rbase + mt * 16 + h * 8;
                float* orow = out + row * D_ + n0 + wn * 64 + c0;
#pragma unroll
                for (int nt = 0; nt < 2; nt++)
#pragma unroll
                    for (int hi = 0; hi < 2; hi++) {
                        *reinterpret_cast<float2*>(orow + nt * 16 + hi * 8) =
                            make_float2(acc0[mt][nt][hi][2 * h + 0], acc0[mt][nt][hi][2 * h + 1]);
                        *reinterpret_cast<float2*>(orow + 32 + nt * 16 + hi * 8) =
                            make_float2(acc1[mt][nt][hi][2 * h + 0], acc1[mt][nt][hi][2 * h + 1]);
                    }
            }
        }
    }
}

// ---------------- launch ----------------
extern "C" void kernel_launch(void* const* d_in, const int* in_sizes, int n_in,
                              void* d_out, int out_size) {
    const float* x  = (const float*)d_in[0];
    const float* w1 = (const float*)d_in[1];
    const float* w3 = (const float*)d_in[2];
    const float* w2 = (const float*)d_in[3];
    float* out = (float*)d_out;

    void *pxh, *pw1t, *pw3t, *pw2t;
    cudaGetSymbolAddress(&pxh,  g_xh);
    cudaGetSymbolAddress(&pw1t, g_w1t);
    cudaGetSymbolAddress(&pw3t, g_w3t);
    cudaGetSymbolAddress(&pw2t, g_w2t);

    cudaFuncSetAttribute(gemm_mma<1>, cudaFuncAttributeMaxDynamicSharedMemorySize, DYNSM);
    cudaFuncSetAttribute(gemm_mma<0>, cudaFuncAttributeMaxDynamicSharedMemorySize, DYNSM);

    const int nx4 = (int)((size_t)B_ * E_ * C_ * D_ / 4);
    cvt_kernel<<<(nx4 + 255) / 256, 256>>>((const float4*)x, (__half2*)pxh, nx4);

    dim3 tb(32, 8);
    cvtT_kernel<<<dim3(F_ / 32, D_ / 32, E_), tb>>>(w1, (__half*)pw1t, D_, F_);
    cvtT_kernel<<<dim3(F_ / 32, D_ / 32, E_), tb>>>(w3, (__half*)pw3t, D_, F_);
    cvtT_kernel<<<dim3(D_ / 32, F_ / 32, E_), tb>>>(w2, (__half*)pw2t, F_, D_);

    gemm_mma<1><<<dim3(F_ / 128, C_ / 128, B_ * E_), 512, DYNSM>>>(nullptr);
    gemm_mma<0><<<dim3(D_ / 256, C_ / 128, B_ * E_), 512, DYNSM>>>(out);
}

// round 8
// speedup vs baseline: 1.4483x; 1.1553x over previous
#include <cuda_runtime.h>
#include <cuda_fp16.h>
#include <cstdint>

// ---------------- problem dims ----------------
constexpr int B_ = 4, E_ = 8, C_ = 2048, D_ = 1024, F_ = 2816;

// Packed tile geometry: A tiles 128x64 halfs (16KB), B tiles 256x64 halfs (32KB),
// both SW128-swizzled within the tile.
constexpr int TILE_A = 16384;   // bytes
constexpr int TILE_B = 32768;   // bytes

// ---------------- device scratch (allocation-free) ----------------
// X packed:  [be][mblk 16][kblk 16] tiles of 128x64
__device__ __half g_xa [(size_t)B_ * E_ * C_ * D_];
// W1+W3 packed: [e][nblk 22][kblk 16] tiles of 256x64 (rows 0-127 w1, 128-255 w3)
__device__ __half g_wa [(size_t)E_ * 22 * 16 * 16384];
// W2 packed: [e][nblk 4][kblk 44] tiles of 256x64
__device__ __half g_w2a[(size_t)E_ * 4 * 44 * 16384];
// H packed:  [be][mblk 16][kblk 44] tiles of 128x64
__device__ __half g_ha [(size_t)B_ * E_ * C_ * F_];

// ---------------- PTX helpers ----------------
__device__ __forceinline__ uint32_t smem_u32(const void* p) {
    return (uint32_t)__cvta_generic_to_shared(p);
}
__device__ __forceinline__ uint32_t swz(uint32_t off) { return off ^ ((off >> 3) & 0x70); }

__device__ __forceinline__ void bulk_cp(uint32_t dst, const void* src, uint32_t bytes,
                                        uint32_t mbar) {
    asm volatile(
        "cp.async.bulk.shared::cluster.global.mbarrier::complete_tx::bytes "
        "[%0], [%1], %2, [%3];"
        ::"r"(dst), "l"(src), "r"(bytes), "r"(mbar) : "memory");
}
__device__ __forceinline__ void mbar_init(uint32_t a, uint32_t cnt) {
    asm volatile("mbarrier.init.shared.b64 [%0], %1;" ::"r"(a), "r"(cnt) : "memory");
}
__device__ __forceinline__ void mbar_expect_tx(uint32_t a, uint32_t bytes) {
    asm volatile("mbarrier.arrive.expect_tx.shared.b64 _, [%0], %1;"
                 ::"r"(a), "r"(bytes) : "memory");
}
__device__ __forceinline__ void mbar_wait(uint32_t a, uint32_t parity) {
    asm volatile(
        "{\n\t.reg .pred P;\n"
        "WL_%=:\n\t"
        "mbarrier.try_wait.parity.acquire.cta.shared::cta.b64 P, [%0], %1, 0x989680;\n\t"
        "@P bra WD_%=;\n\t"
        "bra WL_%=;\n"
        "WD_%=:\n\t}"
        ::"r"(a), "r"(parity) : "memory");
}
__device__ __forceinline__ void ldsm4(uint32_t* r, uint32_t addr) {
    asm volatile("ldmatrix.sync.aligned.m8n8.x4.shared.b16 {%0,%1,%2,%3}, [%4];"
                 : "=r"(r[0]), "=r"(r[1]), "=r"(r[2]), "=r"(r[3])
                 : "r"(addr));
}
__device__ __forceinline__ void mma16816(float* d, const uint32_t* a, uint32_t b0, uint32_t b1) {
    asm volatile(
        "mma.sync.aligned.m16n8k16.row.col.f32.f16.f16.f32 "
        "{%0,%1,%2,%3}, {%4,%5,%6,%7}, {%8,%9}, {%0,%1,%2,%3};"
        : "+f"(d[0]), "+f"(d[1]), "+f"(d[2]), "+f"(d[3])
        : "r"(a[0]), "r"(a[1]), "r"(a[2]), "r"(a[3]), "r"(b0), "r"(b1));
}

// ---------------- pack kernels ----------------
// X: [be][C][D] fp32 -> packed swizzled A tiles
__global__ void pack_x(const float4* __restrict__ x) {
    const int be = blockIdx.z, mb = blockIdx.y, kb = blockIdx.x;
    const float4* src = x + ((size_t)be * C_ + mb * 128) * (D_ / 4) + kb * 16;
    char* dst = (char*)g_xa + (((size_t)be * 16 + mb) * 16 + kb) * TILE_A;
    const int tid = threadIdx.x;
#pragma unroll
    for (int j = 0; j < 8; j++) {
        int t = tid + j * 256;          // 0..2047
        int r = t >> 4, c = t & 15;     // row 0..127, float4-chunk 0..15
        float4 v = src[(size_t)r * (D_ / 4) + c];
        uint2 p;
        __half2 h0 = __floats2half2_rn(v.x, v.y);
        __half2 h1 = __floats2half2_rn(v.z, v.w);
        p.x = *reinterpret_cast<uint32_t*>(&h0);
        p.y = *reinterpret_cast<uint32_t*>(&h1);
        *reinterpret_cast<uint2*>(dst + swz(r * 128 + c * 8)) = p;
    }
}

// w1/w3: [e][D][F] fp32 -> rows (rowoff + f%128) of tile (e, f/128, d/64)
__global__ void pack_w13(const float* __restrict__ w, int rowoff) {
    __shared__ float t[32][33];
    const int e = blockIdx.z;
    const int f0 = blockIdx.x * 32, d0 = blockIdx.y * 32;
    const float* src = w + (size_t)e * D_ * F_;
    const int tx = threadIdx.x, ty = threadIdx.y;   // 32 x 8
#pragma unroll
    for (int i = 0; i < 4; i++)
        t[ty + 8 * i][tx] = src[(size_t)(d0 + ty + 8 * i) * F_ + f0 + tx];
    __syncthreads();
    const int lin = ty * 32 + tx;                   // 0..255
#pragma unroll
    for (int i = 0; i < 2; i++) {
        int idx = lin + 256 * i;                    // 0..511
        int fl = idx >> 4, dp = idx & 15;           // f-local, d-pair
        int n = f0 + fl;
        int nb = n >> 7, row = (n & 127) + rowoff;
        int d = d0 + 2 * dp;
        int kb = d >> 6, cd = d & 63;
        char* dst = (char*)g_wa + (((size_t)e * 22 + nb) * 16 + kb) * TILE_B;
        *reinterpret_cast<__half2*>(dst + swz(row * 128 + cd * 2)) =
            __floats2half2_rn(t[2 * dp][fl], t[2 * dp + 1][fl]);
    }
}

// w2: [e][F][D] fp32 -> rows d%256 of tile (e, d/256, f/64)
__global__ void pack_w2(const float* __restrict__ w) {
    __shared__ float t[32][33];
    const int e = blockIdx.z;
    const int d0 = blockIdx.x * 32, f0 = blockIdx.y * 32;
    const float* src = w + (size_t)e * F_ * D_;
    const int tx = threadIdx.x, ty = threadIdx.y;
#pragma unroll
    for (int i = 0; i < 4; i++)
        t[ty + 8 * i][tx] = src[(size_t)(f0 + ty + 8 * i) * D_ + d0 + tx];
    __syncthreads();
    const int lin = ty * 32 + tx;
#pragma unroll
    for (int i = 0; i < 2; i++) {
        int idx = lin + 256 * i;
        int dl = idx >> 4, fp = idx & 15;           // d-local, f-pair
        int n = d0 + dl;
        int nb = n >> 8, row = n & 255;
        int f = f0 + 2 * fp;
        int kb = f >> 6, cf = f & 63;
        char* dst = (char*)g_w2a + (((size_t)e * 4 + nb) * 44 + kb) * TILE_B;
        *reinterpret_cast<__half2*>(dst + swz(row * 128 + cf * 2)) =
            __floats2half2_rn(t[2 * fp][dl], t[2 * fp + 1][dl]);
    }
}

// ============================================================
// mma.sync GEMM with whole-tile bulk-async loads.
// 512 threads, CTA tile 128(M) x 256(B-rows), BK=64, 4 stages.
// Per stage: ONE 16KB A bulk copy + ONE 32KB B bulk copy -> mbarrier.
// SMEM layout = packed gmem layout (SW128 swizzled, 128B rows).
// GEMM1: B rows 0-127 = w1, 128-255 = w3; SwiGLU in regs -> packed H tiles.
// GEMM2: B = w2 tiles -> out fp32 (normal layout).
// ============================================================
constexpr int STG   = TILE_A + TILE_B;   // 49152
constexpr int DYNSM = 4 * STG;           // 196608

template <int G1>
__global__ __launch_bounds__(512, 1) void gemm_mma(float* __restrict__ out) {
    extern __shared__ __align__(128) char smem[];
    __shared__ __align__(8) uint64_t mbars[4];

    const int tid  = threadIdx.x;
    const int wid  = tid >> 5;
    const int lane = tid & 31;
    const int be   = blockIdx.z, e = be & 7;
    const int mblk = blockIdx.y;
    const int nblk = blockIdx.x;

    constexpr int NK = G1 ? 16 : 44;

    const char* Atile;
    const char* Btile;
    if (G1) {
        Atile = (const char*)g_xa + (((size_t)be * 16 + mblk) * 16) * TILE_A;
        Btile = (const char*)g_wa + (((size_t)e * 22 + nblk) * 16) * TILE_B;
    } else {
        Atile = (const char*)g_ha  + (((size_t)be * 16 + mblk) * 44) * TILE_A;
        Btile = (const char*)g_w2a + (((size_t)e * 4 + nblk) * 44) * TILE_B;
    }

    const uint32_t sb = smem_u32(smem);
    const uint32_t mb = smem_u32(mbars);

    if (tid == 0) {
#pragma unroll
        for (int i = 0; i < 4; i++) mbar_init(mb + 8 * i, 1);
    }
    __syncthreads();

    auto issue = [&](int s, int kt) {
        if (tid == 0) {
            mbar_expect_tx(mb + 8 * s, STG);
            bulk_cp(sb + s * STG, Atile + (size_t)kt * TILE_A, TILE_A, mb + 8 * s);
            bulk_cp(sb + s * STG + TILE_A, Btile + (size_t)kt * TILE_B, TILE_B, mb + 8 * s);
        }
    };

    issue(0, 0);
    issue(1, 1);
    issue(2, 2);

    const int wm = wid >> 2;           // 0..3 : M rows [wm*32, +32)
    const int wn = wid & 3;            // 0..3
    const int lr = lane & 15;
    const int lk = (lane >> 4) * 16;

    float acc0[2][2][2][4], acc1[2][2][2][4];
#pragma unroll
    for (int a = 0; a < 2; a++)
#pragma unroll
        for (int b = 0; b < 2; b++)
#pragma unroll
            for (int c = 0; c < 2; c++)
#pragma unroll
                for (int q = 0; q < 4; q++) { acc0[a][b][c][q] = 0.f; acc1[a][b][c][q] = 0.f; }

    for (int kt = 0; kt < NK; kt++) {
        const int s = kt & 3;

        __syncthreads();   // all warps done consuming stage kt-1 -> buffer (kt+3)&3 free
        if (kt + 3 < NK) issue((kt + 3) & 3, kt + 3);
        mbar_wait(mb + 8 * s, (kt >> 2) & 1);

        const uint32_t sA = sb + s * STG;
        const uint32_t sB = sA + TILE_A;

#pragma unroll
        for (int kk = 0; kk < 4; kk++) {
            uint32_t af[2][4];
#pragma unroll
            for (int mt = 0; mt < 2; mt++)
                ldsm4(af[mt], sA + swz((wm * 32 + mt * 16 + lr) * 128 + kk * 32 + lk));

            uint32_t b0r[2][4], b1r[2][4];
#pragma unroll
            for (int nt = 0; nt < 2; nt++) {
                if (G1) {
                    ldsm4(b0r[nt], sB + swz((wn * 32 + nt * 16 + lr) * 128 + kk * 32 + lk));
                    ldsm4(b1r[nt], sB + swz((128 + wn * 32 + nt * 16 + lr) * 128 + kk * 32 + lk));
                } else {
                    ldsm4(b0r[nt], sB + swz((wn * 64 + nt * 16 + lr) * 128 + kk * 32 + lk));
                    ldsm4(b1r[nt], sB + swz((wn * 64 + 32 + nt * 16 + lr) * 128 + kk * 32 + lk));
                }
            }
#pragma unroll
            for (int mt = 0; mt < 2; mt++)
#pragma unroll
                for (int nt = 0; nt < 2; nt++)
#pragma unroll
                    for (int hi = 0; hi < 2; hi++) {
                        mma16816(acc0[mt][nt][hi], af[mt], b0r[nt][hi], b0r[nt][hi + 2]);
                        mma16816(acc1[mt][nt][hi], af[mt], b1r[nt][hi], b1r[nt][hi + 2]);
                    }
        }
    }

    // ---------------- epilogue ----------------
    const int lr4 = lane >> 2;
    const int c0  = (lane & 3) * 2;

    if (G1) {
        // SwiGLU -> packed-swizzled H tiles (A-tile layout for GEMM2)
#pragma unroll
        for (int mt = 0; mt < 2; mt++) {
#pragma unroll
            for (int h = 0; h < 2; h++) {
                const int r128 = wm * 32 + mt * 16 + h * 8 + lr4;   // row in 128-tile
#pragma unroll
                for (int nt = 0; nt < 2; nt++)
#pragma unroll
                    for (int hi = 0; hi < 2; hi++) {
                        const int nc = wn * 32 + nt * 16 + hi * 8 + c0;   // 0..127
                        float g0 = acc0[mt][nt][hi][2 * h + 0], g1 = acc0[mt][nt][hi][2 * h + 1];
                        float u0 = acc1[mt][nt][hi][2 * h + 0], u1 = acc1[mt][nt][hi][2 * h + 1];
                        float h0 = u0 * g0 / (1.0f + __expf(-g0));
                        float h1 = u1 * g1 / (1.0f + __expf(-g1));
                        const int kb = nblk * 2 + (nc >> 6);
                        char* dst = (char*)g_ha +
                                    (((size_t)be * 16 + mblk) * 44 + kb) * TILE_A;
                        *reinterpret_cast<__half2*>(dst + swz(r128 * 128 + (nc & 63) * 2)) =
                            __floats2half2_rn(h0, h1);
                    }
            }
        }
    } else {
        // fp32 out, normal layout
        const int rbase = mblk * 128 + wm * 32 + lr4;
        const int n0    = nblk * 256;
#pragma unroll
        for (int mt = 0; mt < 2; mt++) {
#pragma unroll
            for (int h = 0; h < 2; h++) {
                const size_t row = (size_t)be * C_ + rbase + mt * 16 + h * 8;
                float* orow = out + row * D_ + n0 + wn * 64 + c0;
#pragma unroll
                for (int nt = 0; nt < 2; nt++)
#pragma unroll
                    for (int hi = 0; hi < 2; hi++) {
                        *reinterpret_cast<float2*>(orow + nt * 16 + hi * 8) =
                            make_float2(acc0[mt][nt][hi][2 * h + 0], acc0[mt][nt][hi][2 * h + 1]);
                        *reinterpret_cast<float2*>(orow + 32 + nt * 16 + hi * 8) =
                            make_float2(acc1[mt][nt][hi][2 * h + 0], acc1[mt][nt][hi][2 * h + 1]);
                    }
            }
        }
    }
}

// ---------------- launch ----------------
extern "C" void kernel_launch(void* const* d_in, const int* in_sizes, int n_in,
                              void* d_out, int out_size) {
    const float* x  = (const float*)d_in[0];
    const float* w1 = (const float*)d_in[1];
    const float* w3 = (const float*)d_in[2];
    const float* w2 = (const float*)d_in[3];
    float* out = (float*)d_out;

    cudaFuncSetAttribute(gemm_mma<1>, cudaFuncAttributeMaxDynamicSharedMemorySize, DYNSM);
    cudaFuncSetAttribute(gemm_mma<0>, cudaFuncAttributeMaxDynamicSharedMemorySize, DYNSM);

    dim3 tb(32, 8);
    pack_x  <<<dim3(16, 16, 32), 256>>>((const float4*)x);
    pack_w13<<<dim3(88, 32, 8), tb>>>(w1, 0);
    pack_w13<<<dim3(88, 32, 8), tb>>>(w3, 128);
    pack_w2 <<<dim3(32, 88, 8), tb>>>(w2);

    gemm_mma<1><<<dim3(22, 16, 32), 512, DYNSM>>>(nullptr);
    gemm_mma<0><<<dim3(4, 16, 32), 512, DYNSM>>>(out);
}

// round 9
// speedup vs baseline: 1.5408x; 1.0639x over previous
#include <cuda_runtime.h>
#include <cuda_fp16.h>
#include <cstdint>

// ---------------- problem dims ----------------
constexpr int B_ = 4, E_ = 8, C_ = 2048, D_ = 1024, F_ = 2816;

// Packed tile geometry: A tiles 128x64 halfs (16KB), B tiles 256x64 halfs (32KB),
// both SW128-swizzled within the tile.
constexpr int TILE_A = 16384;   // bytes
constexpr int TILE_B = 32768;   // bytes

// ---------------- device scratch (allocation-free) ----------------
__device__ __half g_xa [(size_t)B_ * E_ * C_ * D_];            // X tiles [be][mb 16][kb 16]
__device__ __half g_wa [(size_t)E_ * 22 * 16 * 16384];         // W1|W3 tiles [e][nb 22][kb 16]
__device__ __half g_w2a[(size_t)E_ * 4 * 44 * 16384];          // W2 tiles [e][nb 4][kb 44]
__device__ __half g_ha [(size_t)B_ * E_ * C_ * F_];            // H tiles [be][mb 16][kb 44]

// ---------------- PTX helpers ----------------
__device__ __forceinline__ uint32_t smem_u32(const void* p) {
    return (uint32_t)__cvta_generic_to_shared(p);
}
__device__ __forceinline__ uint32_t swz(uint32_t off) { return off ^ ((off >> 3) & 0x70); }

__device__ __forceinline__ void bulk_cp(uint32_t dst, const void* src, uint32_t bytes,
                                        uint32_t mbar) {
    asm volatile(
        "cp.async.bulk.shared::cluster.global.mbarrier::complete_tx::bytes "
        "[%0], [%1], %2, [%3];"
        ::"r"(dst), "l"(src), "r"(bytes), "r"(mbar) : "memory");
}
__device__ __forceinline__ void mbar_init(uint32_t a, uint32_t cnt) {
    asm volatile("mbarrier.init.shared.b64 [%0], %1;" ::"r"(a), "r"(cnt) : "memory");
}
__device__ __forceinline__ void mbar_expect_tx(uint32_t a, uint32_t bytes) {
    asm volatile("mbarrier.arrive.expect_tx.shared.b64 _, [%0], %1;"
                 ::"r"(a), "r"(bytes) : "memory");
}
__device__ __forceinline__ void mbar_wait(uint32_t a, uint32_t parity) {
    asm volatile(
        "{\n\t.reg .pred P;\n"
        "WL_%=:\n\t"
        "mbarrier.try_wait.parity.acquire.cta.shared::cta.b64 P, [%0], %1, 0x989680;\n\t"
        "@P bra WD_%=;\n\t"
        "bra WL_%=;\n"
        "WD_%=:\n\t}"
        ::"r"(a), "r"(parity) : "memory");
}
__device__ __forceinline__ void ldsm4(uint32_t* r, uint32_t addr) {
    asm volatile("ldmatrix.sync.aligned.m8n8.x4.shared.b16 {%0,%1,%2,%3}, [%4];"
                 : "=r"(r[0]), "=r"(r[1]), "=r"(r[2]), "=r"(r[3])
                 : "r"(addr));
}
__device__ __forceinline__ void mma16816(float* d, const uint32_t* a, uint32_t b0, uint32_t b1) {
    asm volatile(
        "mma.sync.aligned.m16n8k16.row.col.f32.f16.f16.f32 "
        "{%0,%1,%2,%3}, {%4,%5,%6,%7}, {%8,%9}, {%0,%1,%2,%3};"
        : "+f"(d[0]), "+f"(d[1]), "+f"(d[2]), "+f"(d[3])
        : "r"(a[0]), "r"(a[1]), "r"(a[2]), "r"(a[3]), "r"(b0), "r"(b1));
}

// ---------------- pack kernels ----------------
__global__ void pack_x(const float4* __restrict__ x) {
    const int be = blockIdx.z, mb = blockIdx.y, kb = blockIdx.x;
    const float4* src = x + ((size_t)be * C_ + mb * 128) * (D_ / 4) + kb * 16;
    char* dst = (char*)g_xa + (((size_t)be * 16 + mb) * 16 + kb) * TILE_A;
    const int tid = threadIdx.x;
#pragma unroll
    for (int j = 0; j < 8; j++) {
        int t = tid + j * 256;
        int r = t >> 4, c = t & 15;
        float4 v = src[(size_t)r * (D_ / 4) + c];
        uint2 p;
        __half2 h0 = __floats2half2_rn(v.x, v.y);
        __half2 h1 = __floats2half2_rn(v.z, v.w);
        p.x = *reinterpret_cast<uint32_t*>(&h0);
        p.y = *reinterpret_cast<uint32_t*>(&h1);
        *reinterpret_cast<uint2*>(dst + swz(r * 128 + c * 8)) = p;
    }
}

__global__ void pack_w13(const float* __restrict__ w, int rowoff) {
    __shared__ float t[32][33];
    const int e = blockIdx.z;
    const int f0 = blockIdx.x * 32, d0 = blockIdx.y * 32;
    const float* src = w + (size_t)e * D_ * F_;
    const int tx = threadIdx.x, ty = threadIdx.y;
#pragma unroll
    for (int i = 0; i < 4; i++)
        t[ty + 8 * i][tx] = src[(size_t)(d0 + ty + 8 * i) * F_ + f0 + tx];
    __syncthreads();
    const int lin = ty * 32 + tx;
#pragma unroll
    for (int i = 0; i < 2; i++) {
        int idx = lin + 256 * i;
        int fl = idx >> 4, dp = idx & 15;
        int n = f0 + fl;
        int nb = n >> 7, row = (n & 127) + rowoff;
        int d = d0 + 2 * dp;
        int kb = d >> 6, cd = d & 63;
        char* dst = (char*)g_wa + (((size_t)e * 22 + nb) * 16 + kb) * TILE_B;
        *reinterpret_cast<__half2*>(dst + swz(row * 128 + cd * 2)) =
            __floats2half2_rn(t[2 * dp][fl], t[2 * dp + 1][fl]);
    }
}

__global__ void pack_w2(const float* __restrict__ w) {
    __shared__ float t[32][33];
    const int e = blockIdx.z;
    const int d0 = blockIdx.x * 32, f0 = blockIdx.y * 32;
    const float* src = w + (size_t)e * F_ * D_;
    const int tx = threadIdx.x, ty = threadIdx.y;
#pragma unroll
    for (int i = 0; i < 4; i++)
        t[ty + 8 * i][tx] = src[(size_t)(f0 + ty + 8 * i) * D_ + d0 + tx];
    __syncthreads();
    const int lin = ty * 32 + tx;
#pragma unroll
    for (int i = 0; i < 2; i++) {
        int idx = lin + 256 * i;
        int dl = idx >> 4, fp = idx & 15;
        int n = d0 + dl;
        int nb = n >> 8, row = n & 255;
        int f = f0 + 2 * fp;
        int kb = f >> 6, cf = f & 63;
        char* dst = (char*)g_w2a + (((size_t)e * 4 + nb) * 44 + kb) * TILE_B;
        *reinterpret_cast<__half2*>(dst + swz(row * 128 + cf * 2)) =
            __floats2half2_rn(t[2 * fp][dl], t[2 * fp + 1][dl]);
    }
}

// ============================================================
// mma.sync GEMM, whole-tile bulk-async loads, PAIR-UNROLLED stages.
// 512 threads, CTA tile 128(M) x 256(B-rows), BK=64 per stage, 4 stages.
// Outer loop: 2 stages per iteration -> 1 __syncthreads + 1 issue-burst / 2 stages.
// ============================================================
constexpr int STG   = TILE_A + TILE_B;   // 49152
constexpr int DYNSM = 4 * STG;           // 196608

template <int G1>
__global__ __launch_bounds__(512, 1) void gemm_mma(float* __restrict__ out) {
    extern __shared__ __align__(128) char smem[];
    __shared__ __align__(8) uint64_t mbars[4];

    const int tid  = threadIdx.x;
    const int wid  = tid >> 5;
    const int lane = tid & 31;
    const int be   = blockIdx.z, e = be & 7;
    const int mblk = blockIdx.y;
    const int nblk = blockIdx.x;

    constexpr int NK = G1 ? 16 : 44;     // both even

    const char* Atile;
    const char* Btile;
    if (G1) {
        Atile = (const char*)g_xa + (((size_t)be * 16 + mblk) * 16) * TILE_A;
        Btile = (const char*)g_wa + (((size_t)e * 22 + nblk) * 16) * TILE_B;
    } else {
        Atile = (const char*)g_ha  + (((size_t)be * 16 + mblk) * 44) * TILE_A;
        Btile = (const char*)g_w2a + (((size_t)e * 4 + nblk) * 44) * TILE_B;
    }

    const uint32_t sb = smem_u32(smem);
    const uint32_t mb = smem_u32(mbars);

    if (tid == 0) {
#pragma unroll
        for (int i = 0; i < 4; i++) mbar_init(mb + 8 * i, 1);
    }
    __syncthreads();

    auto issue = [&](int kt) {
        const int s = kt & 3;
        mbar_expect_tx(mb + 8 * s, STG);
        bulk_cp(sb + s * STG, Atile + (size_t)kt * TILE_A, TILE_A, mb + 8 * s);
        bulk_cp(sb + s * STG + TILE_A, Btile + (size_t)kt * TILE_B, TILE_B, mb + 8 * s);
    };

    if (tid == 0) {
        issue(0); issue(1); issue(2); issue(3);
    }

    const int wm = wid >> 2;
    const int wn = wid & 3;
    const int lr = lane & 15;
    const int lk = (lane >> 4) * 16;

    float acc0[2][2][2][4], acc1[2][2][2][4];
#pragma unroll
    for (int a = 0; a < 2; a++)
#pragma unroll
        for (int b = 0; b < 2; b++)
#pragma unroll
            for (int c = 0; c < 2; c++)
#pragma unroll
                for (int q = 0; q < 4; q++) { acc0[a][b][c][q] = 0.f; acc1[a][b][c][q] = 0.f; }

    // consume one 64-k stage from buffer s
    auto consume = [&](int kt) {
        const int s = kt & 3;
        mbar_wait(mb + 8 * s, (kt >> 2) & 1);
        const uint32_t sA = sb + s * STG;
        const uint32_t sB = sA + TILE_A;
#pragma unroll
        for (int kk = 0; kk < 4; kk++) {
            uint32_t af[2][4];
#pragma unroll
            for (int mt = 0; mt < 2; mt++)
                ldsm4(af[mt], sA + swz((wm * 32 + mt * 16 + lr) * 128 + kk * 32 + lk));

            uint32_t b0r[2][4], b1r[2][4];
#pragma unroll
            for (int nt = 0; nt < 2; nt++) {
                if (G1) {
                    ldsm4(b0r[nt], sB + swz((wn * 32 + nt * 16 + lr) * 128 + kk * 32 + lk));
                    ldsm4(b1r[nt], sB + swz((128 + wn * 32 + nt * 16 + lr) * 128 + kk * 32 + lk));
                } else {
                    ldsm4(b0r[nt], sB + swz((wn * 64 + nt * 16 + lr) * 128 + kk * 32 + lk));
                    ldsm4(b1r[nt], sB + swz((wn * 64 + 32 + nt * 16 + lr) * 128 + kk * 32 + lk));
                }
            }
#pragma unroll
            for (int mt = 0; mt < 2; mt++)
#pragma unroll
                for (int nt = 0; nt < 2; nt++)
#pragma unroll
                    for (int hi = 0; hi < 2; hi++) {
                        mma16816(acc0[mt][nt][hi], af[mt], b0r[nt][hi], b0r[nt][hi + 2]);
                        mma16816(acc1[mt][nt][hi], af[mt], b1r[nt][hi], b1r[nt][hi + 2]);
                    }
        }
    };

    // pair-unrolled main loop: one barrier + one issue-burst per 2 stages
    for (int kt = 0; kt < NK; kt += 2) {
        if (kt >= 2) {
            __syncthreads();   // all warps done with stages kt-2, kt-1 -> their buffers free
            if (tid == 0) {
                if (kt + 2 < NK) issue(kt + 2);
                if (kt + 3 < NK) issue(kt + 3);
            }
        }
        consume(kt);
        consume(kt + 1);
    }

    // ---------------- epilogue ----------------
    const int lr4 = lane >> 2;
    const int c0  = (lane & 3) * 2;

    if (G1) {
#pragma unroll
        for (int mt = 0; mt < 2; mt++) {
#pragma unroll
            for (int h = 0; h < 2; h++) {
                const int r128 = wm * 32 + mt * 16 + h * 8 + lr4;
#pragma unroll
                for (int nt = 0; nt < 2; nt++)
#pragma unroll
                    for (int hi = 0; hi < 2; hi++) {
                        const int nc = wn * 32 + nt * 16 + hi * 8 + c0;
                        float g0 = acc0[mt][nt][hi][2 * h + 0], g1 = acc0[mt][nt][hi][2 * h + 1];
                        float u0 = acc1[mt][nt][hi][2 * h + 0], u1 = acc1[mt][nt][hi][2 * h + 1];
                        float h0 = u0 * g0 / (1.0f + __expf(-g0));
                        float h1 = u1 * g1 / (1.0f + __expf(-g1));
                        const int kb = nblk * 2 + (nc >> 6);
                        char* dst = (char*)g_ha +
                                    (((size_t)be * 16 + mblk) * 44 + kb) * TILE_A;
                        *reinterpret_cast<__half2*>(dst + swz(r128 * 128 + (nc & 63) * 2)) =
                            __floats2half2_rn(h0, h1);
                    }
            }
        }
    } else {
        const int rbase = mblk * 128 + wm * 32 + lr4;
        const int n0    = nblk * 256;
#pragma unroll
        for (int mt = 0; mt < 2; mt++) {
#pragma unroll
            for (int h = 0; h < 2; h++) {
                const size_t row = (size_t)be * C_ + rbase + mt * 16 + h * 8;
                float* orow = out + row * D_ + n0 + wn * 64 + c0;
#pragma unroll
                for (int nt = 0; nt < 2; nt++)
#pragma unroll
                    for (int hi = 0; hi < 2; hi++) {
                        *reinterpret_cast<float2*>(orow + nt * 16 + hi * 8) =
                            make_float2(acc0[mt][nt][hi][2 * h + 0], acc0[mt][nt][hi][2 * h + 1]);
                        *reinterpret_cast<float2*>(orow + 32 + nt * 16 + hi * 8) =
                            make_float2(acc1[mt][nt][hi][2 * h + 0], acc1[mt][nt][hi][2 * h + 1]);
                    }
            }
        }
    }
}

// ---------------- launch ----------------
extern "C" void kernel_launch(void* const* d_in, const int* in_sizes, int n_in,
                              void* d_out, int out_size) {
    const float* x  = (const float*)d_in[0];
    const float* w1 = (const float*)d_in[1];
    const float* w3 = (const float*)d_in[2];
    const float* w2 = (const float*)d_in[3];
    float* out = (float*)d_out;

    cudaFuncSetAttribute(gemm_mma<1>, cudaFuncAttributeMaxDynamicSharedMemorySize, DYNSM);
    cudaFuncSetAttribute(gemm_mma<0>, cudaFuncAttributeMaxDynamicSharedMemorySize, DYNSM);

    dim3 tb(32, 8);
    pack_x  <<<dim3(16, 16, 32), 256>>>((const float4*)x);
    pack_w13<<<dim3(88, 32, 8), tb>>>(w1, 0);
    pack_w13<<<dim3(88, 32, 8), tb>>>(w3, 128);
    pack_w2 <<<dim3(32, 88, 8), tb>>>(w2);

    gemm_mma<1><<<dim3(22, 16, 32), 512, DYNSM>>>(nullptr);
    gemm_mma<0><<<dim3(4, 16, 32), 512, DYNSM>>>(out);
}